// round 17
// baseline (speedup 1.0000x reference)
#include <cuda_runtime.h>
#include <cstdint>
#include <math_constants.h>

#define BATCH 4096
#define VSZ   256
#define NU    129
#define SKIP  25
#define NEGINF (-CUDART_INF_F)
#define FULL  0xFFFFFFFFu

#define ROW_BYTES   516
#define GROUP_ROWS  4
#define GROUP_BYTES 2064                 // 516*4, 16B multiple
#define B_OFF       2112                 // chain-B region: 2064 + 48 pad -> float off 528 (== 16 mod 32 banks)
#define SLOT_BYTES  4176                 // 2112 + 2064
#define PAIR_TX     4128                 // 2 * 2064
#define FIRST_ROW   24                   // 516*24 is 16B aligned
#define NGROUPS     58
#define NSLOTS      3
#define WPB         2                    // warps per block (64 threads); 2 chains per warp

// Strictly monotone float -> uint32 key (order-preserving bijection) + inverse
static __device__ __forceinline__ unsigned fkey(float f) {
    unsigned u = __float_as_uint(f);
    return u ^ ((unsigned)((int)u >> 31) | 0x80000000u);
}
static __device__ __forceinline__ float fkey_inv(unsigned k) {
    unsigned m = (k & 0x80000000u) ? 0x80000000u : 0xFFFFFFFFu;
    return __uint_as_float(k ^ m);
}

static __device__ __forceinline__ uint32_t smem_u32(const void* p) {
    uint32_t a;
    asm("{ .reg .u64 t; cvta.to.shared.u64 t, %1; cvt.u32.u64 %0, t; }" : "=r"(a) : "l"(p));
    return a;
}
static __device__ __forceinline__ void mbar_init(uint32_t mbar, uint32_t cnt) {
    asm volatile("mbarrier.init.shared.b64 [%0], %1;" :: "r"(mbar), "r"(cnt) : "memory");
}
static __device__ __forceinline__ void mbar_expect_tx(uint32_t mbar, uint32_t bytes) {
    asm volatile("mbarrier.arrive.expect_tx.shared.b64 _, [%0], %1;"
                 :: "r"(mbar), "r"(bytes) : "memory");
}
static __device__ __forceinline__ void bulk_g2s(uint32_t dst, const void* src, uint32_t bytes, uint32_t mbar) {
    asm volatile("cp.async.bulk.shared::cta.global.mbarrier::complete_tx::bytes [%0], [%1], %2, [%3];"
                 :: "r"(dst), "l"(src), "r"(bytes), "r"(mbar) : "memory");
}
static __device__ __forceinline__ void mbar_wait(uint32_t mbar, uint32_t parity) {
    uint32_t done;
    asm volatile("{\n\t.reg .pred p;\n\t"
                 "mbarrier.try_wait.parity.acquire.cta.shared::cta.b64 p, [%1], %2;\n\t"
                 "selp.b32 %0, 1, 0, p;\n\t}"
                 : "=r"(done) : "r"(mbar), "r"(parity) : "memory");
    if (!done) {
        asm volatile("{\n\t.reg .pred P1;\n\t"
                     "W_%=:\n\t"
                     "mbarrier.try_wait.parity.acquire.cta.shared::cta.b64 P1, [%0], %1, 0x989680;\n\t"
                     "@P1 bra.uni D_%=;\n\t"
                     "bra.uni W_%=;\n\t"
                     "D_%=:\n\t}"
                     :: "r"(mbar), "r"(parity) : "memory");
    }
}

__global__ void __launch_bounds__(64, 8)
greedy_matching_kernel(const float* __restrict__ x, float* __restrict__ out) {
    // Per warp-slot: [chain A group (2064B) | 48B pad | chain B group (2064B)]
    __shared__ __align__(128) unsigned char sbuf[WPB][NSLOTS][SLOT_BYTES];
    __shared__ __align__(8)   unsigned long long smbar[WPB][NSLOTS];

    const int wib  = threadIdx.x >> 5;
    const int lane = threadIdx.x & 31;
    const int gw   = blockIdx.x * WPB + wib;   // 0..2047
    const int half = lane >> 4;                // 0 = chain A, 1 = chain B
    const int hl   = lane & 15;                // lane within the half
    const int chain = 2 * gw + half;

    const float* __restrict__ baseA = x + (size_t)(2 * gw) * (VSZ * NU);
    const float* __restrict__ baseB = baseA + (size_t)VSZ * NU;
    float* __restrict__ pi = out + BATCH + (size_t)chain * VSZ;

    const uint32_t sb  = smem_u32(&sbuf[wib][0][0]);
    const uint32_t mbb = smem_u32(&smbar[wib][0]);

    // lane 0: init per-warp mbarriers, fence, prime the ring (groups 0..2, both chains)
    if (lane == 0) {
        mbar_init(mbb + 0, 1); mbar_init(mbb + 8, 1); mbar_init(mbb + 16, 1);
        asm volatile("fence.proxy.async.shared::cta;" ::: "memory");
#pragma unroll
        for (int s = 0; s < NSLOTS; ++s) {
            const size_t roff = (size_t)(FIRST_ROW + GROUP_ROWS * s) * NU;
            mbar_expect_tx(mbb + 8u * s, PAIR_TX);
            bulk_g2s(sb + s * SLOT_BYTES,         baseA + roff, GROUP_BYTES, mbb + 8u * s);
            bulk_g2s(sb + s * SLOT_BYTES + B_OFF, baseB + roff, GROUP_BYTES, mbb + 8u * s);
        }
    }
    __syncwarp();

    // Skip phase for this lane's chain: sel = 0, weight 0, no mask change.
    for (int t = hl; t < SKIP; t += 16) pi[t] = 0.0f;

    // Ownership within each 16-lane half: lane hl owns j = hl + 16k (k=0..7,
    // j=0..127) plus, on hl==0, j=128 as a 9th slot (b8). j=0 is the skip:
    // weight forced to 0 via z0 on hl==0, and its bias (tier 0 on hl==0) is
    // never set because of the li!=0 guard. Bias: 0 = available, -inf = matched.
    float b0 = 0.f, b1 = 0.f, b2 = 0.f, b3 = 0.f;
    float b4 = 0.f, b5 = 0.f, b6 = 0.f, b7 = 0.f;
    float b8 = (hl == 0) ? 0.f : NEGINF;
    const float z0 = (hl == 0) ? 0.f : 1.f;
    const unsigned onebit = 1u << lane;
    const unsigned hmask  = 0xFFFFu << (lane & 16);  // this half's member mask
    float size = 0.f;   // per-lane accumulator; per-half butterfly at the end

    // One greedy step for BOTH chains at once. rp = this lane's half region
    // + 129*row (chain B region at float offset 528 => +16 banks, so the two
    // halves' LDS hit disjoint bank sets: conflict-free).
    // Fast path (unique max-key lane in this half): exact global argmax for
    // its chain; does bias update, size add, pi store locally. Multi-lane
    // key tie within a half (~never): exact first-index via partitioned
    // REDUX.min. One redux + one ballot serve both chains.
#define STEP(rp, T)                                                            \
    do {                                                                       \
        float w0 = (rp)[hl];       float w1 = (rp)[hl + 16];                   \
        float w2 = (rp)[hl + 32];  float w3 = (rp)[hl + 48];                   \
        float w4 = (rp)[hl + 64];  float w5 = (rp)[hl + 80];                   \
        float w6 = (rp)[hl + 96];  float w7 = (rp)[hl + 112];                  \
        float w8 = (rp)[128];                                                  \
        float f0 = fmaf(w0, z0, b0);                                           \
        float f1 = w1 + b1;  float f2 = w2 + b2;  float f3 = w3 + b3;          \
        float f4 = w4 + b4;  float f5 = w5 + b5;  float f6 = w6 + b6;          \
        float f7 = w7 + b7;  float f8 = w8 + b8;                               \
        float m01 = fmaxf(f0, f1), m23 = fmaxf(f2, f3);                        \
        float m45 = fmaxf(f4, f5), m67 = fmaxf(f6, f7);                        \
        float m03 = fmaxf(m01, m23), m47 = fmaxf(m45, m67);                    \
        float m07 = fmaxf(m03, m47);                                           \
        float lm  = fmaxf(m07, f8);                                            \
        int j01 = (f1 > f0) ? hl + 16  : hl;                                   \
        int j23 = (f3 > f2) ? hl + 48  : hl + 32;                              \
        int j45 = (f5 > f4) ? hl + 80  : hl + 64;                              \
        int j67 = (f7 > f6) ? hl + 112 : hl + 96;                              \
        int j03 = (m23 > m01) ? j23 : j01;                                     \
        int j47 = (m67 > m45) ? j67 : j45;                                     \
        int j07 = (m47 > m03) ? j47 : j03;                                     \
        int li  = (f8 > m07) ? 128 : j07;                                      \
        unsigned mk = fkey(lm);                                                \
        unsigned gk = __reduce_max_sync(hmask, mk);                            \
        unsigned eq = __ballot_sync(hmask, mk == gk);                          \
        if (__popc(eq) == 1) {                                                 \
            if (eq == onebit) {  /* unique winner of this half */              \
                size += lm;                                                    \
                if (li != 0) {                                                 \
                    int tier = li >> 4;     /* 128>>4 == 8 */                  \
                    if (tier == 0)      b0 = NEGINF;                           \
                    else if (tier == 1) b1 = NEGINF;                           \
                    else if (tier == 2) b2 = NEGINF;                           \
                    else if (tier == 3) b3 = NEGINF;                           \
                    else if (tier == 4) b4 = NEGINF;                           \
                    else if (tier == 5) b5 = NEGINF;                           \
                    else if (tier == 6) b6 = NEGINF;                           \
                    else if (tier == 7) b7 = NEGINF;                           \
                    else                b8 = NEGINF;                           \
                }                                                              \
                pi[T] = __int2float_rn(li);                                    \
            }                                                                  \
        } else {  /* in-half key tie: exact first-index fallback */            \
            unsigned cand = (mk == gk) ? (unsigned)li : FULL;                  \
            int s = (int)__reduce_min_sync(hmask, cand);                       \
            if (s != 0 && (s & 15) == hl) {  /* owner (s==128 -> hl==0) */     \
                int tier = s >> 4;                                             \
                if (tier == 0)      b0 = NEGINF;                               \
                else if (tier == 1) b1 = NEGINF;                               \
                else if (tier == 2) b2 = NEGINF;                               \
                else if (tier == 3) b3 = NEGINF;                               \
                else if (tier == 4) b4 = NEGINF;                               \
                else if (tier == 5) b5 = NEGINF;                               \
                else if (tier == 6) b6 = NEGINF;                               \
                else if (tier == 7) b7 = NEGINF;                               \
                else                b8 = NEGINF;                               \
                size += fkey_inv(gk);                                          \
            }                                                                  \
            if (hl == 0) pi[T] = __int2float_rn(s);                            \
        }                                                                      \
    } while (0)

    int stage = 0, phase = 0;

    // Group 0 (rows 24..27): row 24 is in the skip phase, consume rows 1..3.
    {
        mbar_wait(mbb + 0, 0);
        const float* sp = (const float*)&sbuf[wib][0][0] + half * (B_OFF / 4);
        STEP(sp + 1 * NU, 25);
        STEP(sp + 2 * NU, 26);
        STEP(sp + 3 * NU, 27);
        __syncwarp();   // both halves must finish reading before refill
        if (lane == 0) {
            const size_t roff = (size_t)(FIRST_ROW + GROUP_ROWS * NSLOTS) * NU;
            mbar_expect_tx(mbb + 0, PAIR_TX);
            bulk_g2s(sb + 0,     baseA + roff, GROUP_BYTES, mbb + 0);
            bulk_g2s(sb + B_OFF, baseB + roff, GROUP_BYTES, mbb + 0);
        }
        stage = 1;
    }

    // Groups 1..57: 4 steps each; refill group g+3 while g+3 < 58.
#pragma unroll 1
    for (int g = 1; g < NGROUPS; ++g) {
        mbar_wait(mbb + 8u * stage, phase);
        const float* sp = (const float*)&sbuf[wib][stage][0] + half * (B_OFF / 4);
        const int t0 = FIRST_ROW + GROUP_ROWS * g;
        STEP(sp + 0 * NU, t0 + 0);
        STEP(sp + 1 * NU, t0 + 1);
        STEP(sp + 2 * NU, t0 + 2);
        STEP(sp + 3 * NU, t0 + 3);
        __syncwarp();   // half-warp collectives don't converge the full warp
        if (lane == 0 && g + NSLOTS < NGROUPS) {
            const size_t roff = (size_t)(t0 + GROUP_ROWS * NSLOTS) * NU;
            mbar_expect_tx(mbb + 8u * stage, PAIR_TX);
            bulk_g2s(sb + stage * SLOT_BYTES,         baseA + roff, GROUP_BYTES, mbb + 8u * stage);
            bulk_g2s(sb + stage * SLOT_BYTES + B_OFF, baseB + roff, GROUP_BYTES, mbb + 8u * stage);
        }
        if (++stage == NSLOTS) { stage = 0; phase ^= 1; }
    }

    // Per-half butterfly sum of the per-lane size accumulators.
#pragma unroll
    for (int o = 8; o; o >>= 1) size += __shfl_xor_sync(FULL, size, o, 16);
    if (hl == 0) out[chain] = -size;
}

extern "C" void kernel_launch(void* const* d_in, const int* in_sizes, int n_in,
                              void* d_out, int out_size) {
    const float* x = (const float*)d_in[0];
    float* out = (float*)d_out;
    // 2048 warps, 2 chains each: 1024 blocks x 64 threads
    greedy_matching_kernel<<<BATCH / (2 * WPB), 64>>>(x, out);
}